// round 12
// baseline (speedup 1.0000x reference)
#include <cuda_runtime.h>
#include <cuda_fp16.h>
#include <cstdint>

#define B_ 4
#define T_ 4096
#define C_ 1024
#define H_ 64

#define NQT 32          // 128-query tiles
#define GTILES 8        // k-tiles per attention CTA
#define NPART 144       // sum over qt of ceil((2*qt+2)/8)

// X pre-converted to fp16 half2 words: [b*t][512]
__device__ uint32_t g_xh[B_*T_*512];
// Q: fp16 pairs (half2 words along d), pre-scaled: [b*t][32 words]
__device__ uint32_t g_qh[B_*T_*32];
// K: per 64-key tile, half2-packed B-frag swizzle (pairs along d)
__device__ uint32_t g_kh[B_*64*2048];
// V: pairs along key j
__device__ uint32_t g_vh[B_*64*2048];
// W fp16: [sel][n][k/2] half2 along k
__device__ uint32_t g_wh[3*64*512];

__device__ float g_acc[B_*T_*H_];   // 4 MB unnormalized O accumulator
__device__ float g_lacc[B_*T_];     // 64 KB l accumulator

__device__ __forceinline__ uint32_t h2(float x, float y) {
    __half2 h = __floats2half2_rn(x, y);
    return *reinterpret_cast<uint32_t*>(&h);
}

__device__ __forceinline__ void mma_fp16(float c[4], const uint32_t a[4],
                                         uint32_t b0, uint32_t b1) {
    asm volatile(
        "mma.sync.aligned.m16n8k16.row.col.f32.f16.f16.f32 "
        "{%0,%1,%2,%3}, {%4,%5,%6,%7}, {%8,%9}, {%0,%1,%2,%3};"
        : "+f"(c[0]), "+f"(c[1]), "+f"(c[2]), "+f"(c[3])
        : "r"(a[0]), "r"(a[1]), "r"(a[2]), "r"(a[3]), "r"(b0), "r"(b1));
}

__device__ __forceinline__ void cp16(uint32_t dst, const void* src) {
    asm volatile("cp.async.cg.shared.global [%0], [%1], 16;" :: "r"(dst), "l"(src));
}

// ---------------------------------------------------------------------------
// Kernel 0a: X fp32 -> fp16 half2 words
// ---------------------------------------------------------------------------
__global__ __launch_bounds__(256) void xconv_kernel(const float* __restrict__ x)
{
    int idx = blockIdx.x * 256 + threadIdx.x;   // uint4 units (8 floats each)
    const float4* src = reinterpret_cast<const float4*>(x) + (size_t)idx * 2;
    float4 f0 = src[0], f1 = src[1];
    uint4 u = make_uint4(h2(f0.x, f0.y), h2(f0.z, f0.w),
                         h2(f1.x, f1.y), h2(f1.z, f1.w));
    reinterpret_cast<uint4*>(g_xh)[idx] = u;
}

// ---------------------------------------------------------------------------
// Kernel 0b: W -> fp16 half2 words, [sel][n][k/2]
// ---------------------------------------------------------------------------
__global__ __launch_bounds__(256) void wconv_kernel(
    const float* __restrict__ Wk, const float* __restrict__ Wq,
    const float* __restrict__ Wv)
{
    int idx = blockIdx.x * 256 + threadIdx.x;
    int wi = idx >> 15;
    int r  = idx & 32767;
    int n  = r >> 9;
    int k2 = r & 511;
    const float* W = (wi == 0) ? Wk : ((wi == 1) ? Wq : Wv);
    g_wh[((size_t)(wi*64 + n) << 9) + k2] =
        h2(W[(2*k2)*64 + n], W[(2*k2 + 1)*64 + n]);
}

// ---------------------------------------------------------------------------
// Kernel 1: fused QKV, fp16 mma, 128 threads (R9 shape). X already fp16 in
// gmem -> no conversions in hot loop; A-frags are direct conflict-free LDS.
// ---------------------------------------------------------------------------
#define XST 20           // words per X row (16 data + 4 pad)
#define WST 20
#define XBUF (64*XST)
#define WBUF (192*WST)

__global__ __launch_bounds__(128) void qkv_kernel()
{
    extern __shared__ uint32_t smw[];
    uint32_t* Xs = smw;                  // [2][XBUF]
    uint32_t* Ws = smw + 2*XBUF;         // [2][WBUF]

    const int row0 = blockIdx.x * 64;
    const int tid  = threadIdx.x;
    const int w    = tid >> 5;
    const int lane = tid & 31;
    const int g    = lane >> 2;
    const int q    = lane & 3;

    float acc[4][6][4] = {};

    {
        #pragma unroll
        for (int j = 0; j < 2; j++) {
            int idx = tid + 128*j;
            int r = idx >> 2, c4 = (idx & 3) * 4;
            cp16((uint32_t)__cvta_generic_to_shared(&Xs[r*XST + c4]),
                 &g_xh[((size_t)(row0 + r) << 9) + c4]);
        }
        #pragma unroll
        for (int j = 0; j < 6; j++) {
            int idx = tid + 128*j;
            int r = idx >> 2, c4 = (idx & 3) * 4;
            cp16((uint32_t)__cvta_generic_to_shared(&Ws[r*WST + c4]),
                 &g_wh[((size_t)r << 9) + c4]);
        }
        asm volatile("cp.async.commit_group;");
    }

    for (int ch = 0; ch < 32; ch++) {
        const int p = ch & 1;
        if (ch + 1 < 32) {
            const int k0w = (ch + 1) * 16;
            const int pn = p ^ 1;
            #pragma unroll
            for (int j = 0; j < 2; j++) {
                int idx = tid + 128*j;
                int r = idx >> 2, c4 = (idx & 3) * 4;
                cp16((uint32_t)__cvta_generic_to_shared(&Xs[pn*XBUF + r*XST + c4]),
                     &g_xh[((size_t)(row0 + r) << 9) + k0w + c4]);
            }
            #pragma unroll
            for (int j = 0; j < 6; j++) {
                int idx = tid + 128*j;
                int r = idx >> 2, c4 = (idx & 3) * 4;
                cp16((uint32_t)__cvta_generic_to_shared(&Ws[pn*WBUF + r*WST + c4]),
                     &g_wh[((size_t)r << 9) + k0w + c4]);
            }
            asm volatile("cp.async.commit_group;");
            asm volatile("cp.async.wait_group 1;");
        } else {
            asm volatile("cp.async.wait_group 0;");
        }
        __syncthreads();

        const uint32_t* Xc = Xs + p*XBUF;
        const uint32_t* Wc = Ws + p*WBUF;

        #pragma unroll
        for (int ks = 0; ks < 2; ks++) {
            uint32_t a[4][4];
            #pragma unroll
            for (int m = 0; m < 4; m++) {
                int row = m*16 + g;
                a[m][0] = Xc[row*XST + ks*8 + q];
                a[m][1] = Xc[(row + 8)*XST + ks*8 + q];
                a[m][2] = Xc[row*XST + ks*8 + 4 + q];
                a[m][3] = Xc[(row + 8)*XST + ks*8 + 4 + q];
            }
            #pragma unroll
            for (int j = 0; j < 6; j++) {
                int rn = w*48 + j*8 + g;
                uint32_t b0 = Wc[rn*WST + ks*8 + q];
                uint32_t b1 = Wc[rn*WST + ks*8 + 4 + q];
                #pragma unroll
                for (int m = 0; m < 4; m++)
                    mma_fp16(acc[m][j], a[m], b0, b1);
            }
        }
        __syncthreads();
    }

    // epilogue: sel 0 -> K, 1 -> Q (scaled), 2 -> V (identical to R9)
    const float scale = 0.03125f;
    #pragma unroll
    for (int m = 0; m < 4; m++) {
        #pragma unroll
        for (int j = 0; j < 6; j++) {
            int gcol = w*48 + j*8 + q*2;
            int sel  = gcol >> 6;
            int col  = gcol & 63;
            int row  = row0 + m*16 + g;
            int bb = row >> 12, t = row & 4095;
            int kt = t >> 6, jj = t & 63;
            float a0 = acc[m][j][0], a1 = acc[m][j][1];
            float a2 = acc[m][j][2], a3 = acc[m][j][3];
            if (sel == 0) {
                uint32_t* base = g_kh + (((size_t)bb*64 + kt) << 11);
                int kk = col >> 4, r = col & 15, hi = r >> 3, qq = (r & 7) >> 1;
                base[qq*8 + (jj&7)     + 32*hi + 64*(jj>>3)     + 512*kk] = h2(a0, a1);
                base[qq*8 + ((jj+8)&7) + 32*hi + 64*((jj+8)>>3) + 512*kk] = h2(a2, a3);
            } else if (sel == 1) {
                g_qh[(size_t)row*32     + (col>>1)] = h2(a0*scale, a1*scale);
                g_qh[(size_t)(row+8)*32 + (col>>1)] = h2(a2*scale, a3*scale);
            } else {
                float p0 = __shfl_xor_sync(0xffffffff, a0, 4);
                float p1 = __shfl_xor_sync(0xffffffff, a1, 4);
                float p2 = __shfl_xor_sync(0xffffffff, a2, 4);
                float p3 = __shfl_xor_sync(0xffffffff, a3, 4);
                if ((g & 1) == 0) {
                    uint32_t* base = g_vh + (((size_t)bb*64 + kt) << 11);
                    {
                        int kk = jj >> 4, r = jj & 15, hi = r >> 3, qq = (r & 7) >> 1;
                        int w0 = qq*8 + 32*hi + 512*kk;
                        base[w0 + (col&7)     + 64*(col>>3)]     = h2(a0, p0);
                        base[w0 + ((col+1)&7) + 64*((col+1)>>3)] = h2(a1, p1);
                    }
                    {
                        int j8 = jj + 8;
                        int kk = j8 >> 4, r = j8 & 15, hi = r >> 3, qq = (r & 7) >> 1;
                        int w0 = qq*8 + 32*hi + 512*kk;
                        base[w0 + (col&7)     + 64*(col>>3)]     = h2(a2, p2);
                        base[w0 + ((col+1)&7) + 64*((col+1)>>3)] = h2(a3, p3);
                    }
                }
            }
        }
    }
}

// ---------------------------------------------------------------------------
// Kernel 2: flash attention partial pass (R9 base + diagonal block-skip).
// ---------------------------------------------------------------------------
#define PST 36
#define TILE_W 2048

__global__ __launch_bounds__(256, 2) void attn_part_kernel()
{
    extern __shared__ uint32_t sm[];
    uint32_t* Kf = sm;                       // [2][2048]
    uint32_t* Vf = sm + 2*TILE_W;            // [2][2048]
    uint32_t* Ps = sm + 4*TILE_W;            // [128][PST] (Q staging)

    const int id = blockIdx.x;
    const int b  = blockIdx.y;

    int qt = 0, chunk = id;
    while (chunk >= ((2*qt + 9) >> 3)) { chunk -= (2*qt + 9) >> 3; qt++; }

    const int kb_last = 2*qt + 1;
    const int kb_lo = chunk * GTILES;
    const int kb_hi = min(kb_last, kb_lo + GTILES - 1);

    const int tid = threadIdx.x;
    const int w   = tid >> 5;
    const int lane = tid & 31;
    const int g   = lane >> 2;
    const int q   = lane & 3;
    const int bgq = q*8 + g;

    // stage Q (pre-scaled fp16 words)
    const uint32_t* qg = g_qh + ((size_t)b * T_ + (size_t)qt * 128) * 32;
    for (int i = tid * 4; i < 128 * 32; i += 1024) {
        int r = i >> 5, cc = i & 31;
        *reinterpret_cast<uint4*>(&Ps[r * PST + cc]) =
            *reinterpret_cast<const uint4*>(&qg[r * 32 + cc]);
    }

    const uint32_t* ktile = g_kh + (((size_t)b*64 + kb_lo) << 11);
    const uint32_t* vtile = g_vh + (((size_t)b*64 + kb_lo) << 11);

    #pragma unroll
    for (int j = 0; j < 2; j++) {
        int off = (tid + 256*j) * 4;
        cp16((uint32_t)__cvta_generic_to_shared(&Kf[off]), ktile + off);
        cp16((uint32_t)__cvta_generic_to_shared(&Vf[off]), vtile + off);
    }
    asm volatile("cp.async.commit_group;");

    __syncthreads();

    uint32_t qa[4][4];
    #pragma unroll
    for (int kk = 0; kk < 4; kk++) {
        int row = w * 16 + g;
        qa[kk][0] = Ps[row * PST + kk * 8 + q];
        qa[kk][1] = Ps[(row + 8) * PST + kk * 8 + q];
        qa[kk][2] = Ps[row * PST + kk * 8 + 4 + q];
        qa[kk][3] = Ps[(row + 8) * PST + kk * 8 + 4 + q];
    }

    float o[8][4] = {};
    float l0 = 0.0f, l1 = 0.0f;

    for (int kb = kb_lo; kb <= kb_hi; kb++) {
        const int p = (kb - kb_lo) & 1;
        if (kb < kb_hi) {
            const int pn = p ^ 1;
            const uint32_t* kt2 = g_kh + (((size_t)b*64 + kb + 1) << 11);
            const uint32_t* vt2 = g_vh + (((size_t)b*64 + kb + 1) << 11);
            #pragma unroll
            for (int j = 0; j < 2; j++) {
                int off = (tid + 256*j) * 4;
                cp16((uint32_t)__cvta_generic_to_shared(&Kf[pn*TILE_W + off]), kt2 + off);
                cp16((uint32_t)__cvta_generic_to_shared(&Vf[pn*TILE_W + off]), vt2 + off);
            }
            asm volatile("cp.async.commit_group;");
            asm volatile("cp.async.wait_group 1;");
        } else {
            asm volatile("cp.async.wait_group 0;");
        }
        __syncthreads();

        // fully masked warps on the last diagonal tile: skip compute
        if (kb == kb_last && w < 4) { __syncthreads(); continue; }

        // warp-level unmasked local-column bound for diagonal tiles
        int kmax = 9999;
        if (kb >= 2*qt)
            kmax = (qt*128 + w*16 + 15) - kb*64;   // >= 15 for surviving warps

        const uint32_t* Kc = Kf + p*TILE_W + bgq;
        const uint32_t* Vc = Vf + p*TILE_W + bgq;

        // S = Q @ K^T (skip fully-masked 8-col blocks)
        float s[8][4] = {};
        #pragma unroll
        for (int kk = 0; kk < 4; kk++) {
            #pragma unroll
            for (int n = 0; n < 8; n++) {
                if (n*8 <= kmax) {
                    uint32_t b0 = Kc[512*kk + 64*n];
                    uint32_t b1 = Kc[512*kk + 64*n + 32];
                    mma_fp16(s[n], qa[kk], b0, b1);
                }
            }
        }

        // causal mask on diagonal-crossing k-tiles
        if (kb >= 2*qt) {
            int grow = qt*128 + w*16 + g;
            #pragma unroll
            for (int n = 0; n < 8; n++) {
                int gc = kb*64 + n*8 + q*2;
                if (gc     > grow)     s[n][0] = -1e30f;
                if (gc + 1 > grow)     s[n][1] = -1e30f;
                if (gc     > grow + 8) s[n][2] = -1e30f;
                if (gc + 1 > grow + 8) s[n][3] = -1e30f;
            }
        }

        // fixed-max softmax
        float sum0 = 0.0f, sum1 = 0.0f;
        #pragma unroll
        for (int n = 0; n < 8; n++) {
            s[n][0] = __expf(s[n][0]);
            s[n][1] = __expf(s[n][1]);
            s[n][2] = __expf(s[n][2]);
            s[n][3] = __expf(s[n][3]);
            sum0 += s[n][0] + s[n][1];
            sum1 += s[n][2] + s[n][3];
        }
        sum0 += __shfl_xor_sync(0xffffffff, sum0, 1);
        sum0 += __shfl_xor_sync(0xffffffff, sum0, 2);
        sum1 += __shfl_xor_sync(0xffffffff, sum1, 1);
        sum1 += __shfl_xor_sync(0xffffffff, sum1, 2);
        l0 += sum0;
        l1 += sum1;

        // P in registers -> O += P @ V (skip all-zero 16-key blocks)
        #pragma unroll
        for (int kk = 0; kk < 4; kk++) {
            if (kk*16 <= kmax) {
                uint32_t pa[4];
                pa[0] = h2(s[2*kk][0],   s[2*kk][1]);
                pa[1] = h2(s[2*kk][2],   s[2*kk][3]);
                pa[2] = h2(s[2*kk+1][0], s[2*kk+1][1]);
                pa[3] = h2(s[2*kk+1][2], s[2*kk+1][3]);
                #pragma unroll
                for (int n = 0; n < 8; n++) {
                    uint32_t b0 = Vc[512*kk + 64*n];
                    uint32_t b1 = Vc[512*kk + 64*n + 32];
                    mma_fp16(o[n], pa, b0, b1);
                }
            }
        }
        __syncthreads();
    }

    // accumulate partials atomically
    const int r0 = qt*128 + w*16 + g;
    float* ao0 = g_acc + ((size_t)(b*T_ + r0)) * H_;
    float* ao1 = g_acc + ((size_t)(b*T_ + r0 + 8)) * H_;
    #pragma unroll
    for (int n = 0; n < 8; n++) {
        int col = n * 8 + q * 2;
        atomicAdd(&ao0[col],     o[n][0]);
        atomicAdd(&ao0[col + 1], o[n][1]);
        atomicAdd(&ao1[col],     o[n][2]);
        atomicAdd(&ao1[col + 1], o[n][3]);
    }
    if (q == 0) {
        atomicAdd(&g_lacc[b*T_ + r0],     l0);
        atomicAdd(&g_lacc[b*T_ + r0 + 8], l1);
    }
}

// ---------------------------------------------------------------------------
// Kernel 3: normalize. out[row][h] = g_acc[row][h] / g_lacc[row].
// ---------------------------------------------------------------------------
__global__ __launch_bounds__(256) void attn_norm_kernel(float* __restrict__ out)
{
    int idx = blockIdx.x * 256 + threadIdx.x;
    int row = idx >> 4;
    int c4  = (idx & 15) * 4;
    float invL = 1.0f / g_lacc[row];
    float4 v = *reinterpret_cast<const float4*>(&g_acc[(size_t)row * H_ + c4]);
    v.x *= invL; v.y *= invL; v.z *= invL; v.w *= invL;
    *reinterpret_cast<float4*>(&out[(size_t)row * H_ + c4]) = v;
}

// ---------------------------------------------------------------------------
extern "C" void kernel_launch(void* const* d_in, const int* in_sizes, int n_in,
                              void* d_out, int out_size)
{
    const float* x  = (const float*)d_in[0];
    const float* Wk = (const float*)d_in[1];
    const float* Wq = (const float*)d_in[2];
    const float* Wv = (const float*)d_in[3];
    float* out = (float*)d_out;

    void* acc_ptr = nullptr;
    void* lacc_ptr = nullptr;
    cudaGetSymbolAddress(&acc_ptr, g_acc);
    cudaGetSymbolAddress(&lacc_ptr, g_lacc);
    cudaMemsetAsync(acc_ptr, 0, sizeof(float)*B_*T_*H_);
    cudaMemsetAsync(lacc_ptr, 0, sizeof(float)*B_*T_);

    wconv_kernel<<<384, 256>>>(Wk, Wq, Wv);
    xconv_kernel<<<(B_*T_*512/4)/256, 256>>>(x);

    const int qkv_smem = 2 * (XBUF + WBUF) * (int)sizeof(uint32_t);
    cudaFuncSetAttribute(qkv_kernel,
                         cudaFuncAttributeMaxDynamicSharedMemorySize, qkv_smem);
    qkv_kernel<<<(B_*T_)/64, 128, qkv_smem>>>();

    const int attn_smem = (4*TILE_W + 128*PST) * (int)sizeof(uint32_t);
    cudaFuncSetAttribute(attn_part_kernel,
                         cudaFuncAttributeMaxDynamicSharedMemorySize, attn_smem);
    attn_part_kernel<<<dim3(NPART, B_), 256, attn_smem>>>();

    attn_norm_kernel<<<(B_*T_*16)/256, 256>>>(out);
}

// round 13
// speedup vs baseline: 1.0003x; 1.0003x over previous
#include <cuda_runtime.h>
#include <cuda_fp16.h>
#include <cstdint>

#define B_ 4
#define T_ 4096
#define C_ 1024
#define H_ 64

#define NQT 32          // 128-query tiles
#define GTILES 8        // k-tiles per attention CTA
#define NPART 144       // sum over qt of ceil((2*qt+2)/8)

// Q: fp16 pairs (half2 words along d), pre-scaled: [b*t][32 words]
__device__ uint32_t g_qh[B_*T_*32];
// K: per 64-key tile, half2-packed B-frag swizzle (pairs along d)
__device__ uint32_t g_kh[B_*64*2048];
// V: pairs along key j
__device__ uint32_t g_vh[B_*64*2048];
// W fp16: [sel][n][k/2] half2 along k
__device__ uint32_t g_wh[3*64*512];

__device__ float g_acc[B_*T_*H_];   // 4 MB unnormalized O accumulator
__device__ float g_lacc[B_*T_];     // 64 KB l accumulator

__device__ __forceinline__ uint32_t h2(float x, float y) {
    __half2 h = __floats2half2_rn(x, y);
    return *reinterpret_cast<uint32_t*>(&h);
}

__device__ __forceinline__ void mma_fp16(float c[4], const uint32_t a[4],
                                         uint32_t b0, uint32_t b1) {
    asm volatile(
        "mma.sync.aligned.m16n8k16.row.col.f32.f16.f16.f32 "
        "{%0,%1,%2,%3}, {%4,%5,%6,%7}, {%8,%9}, {%0,%1,%2,%3};"
        : "+f"(c[0]), "+f"(c[1]), "+f"(c[2]), "+f"(c[3])
        : "r"(a[0]), "r"(a[1]), "r"(a[2]), "r"(a[3]), "r"(b0), "r"(b1));
}

__device__ __forceinline__ void cp16(uint32_t dst, const void* src) {
    asm volatile("cp.async.cg.shared.global [%0], [%1], 16;" :: "r"(dst), "l"(src));
}

// ---------------------------------------------------------------------------
// Kernel 0: W -> fp16 half2 words, [sel][n][k/2]
// ---------------------------------------------------------------------------
__global__ __launch_bounds__(256) void wconv_kernel(
    const float* __restrict__ Wk, const float* __restrict__ Wq,
    const float* __restrict__ Wv)
{
    int idx = blockIdx.x * 256 + threadIdx.x;
    int wi = idx >> 15;
    int r  = idx & 32767;
    int n  = r >> 9;
    int k2 = r & 511;
    const float* W = (wi == 0) ? Wk : ((wi == 1) ? Wq : Wv);
    g_wh[((size_t)(wi*64 + n) << 9) + k2] =
        h2(W[(2*k2)*64 + n], W[(2*k2 + 1)*64 + n]);
}

// ---------------------------------------------------------------------------
// Kernel 1: fused QKV, fp16 mma, 256 threads / 8 warps. X fp32 in smem with
// inline cvt at A-frag build (single pass over x). cp.async double-buffered.
// Warp = 32 rows (wr) x 48 cols (wc).
// ---------------------------------------------------------------------------
#define XST 36
#define WST 20
#define XBUF (64*XST)    // floats
#define WBUF (192*WST)   // words

__global__ __launch_bounds__(256) void qkv_kernel(const float* __restrict__ x)
{
    extern __shared__ float smf[];
    float*    Xs = smf;
    uint32_t* Ws = (uint32_t*)(smf + 2*XBUF);

    const int row0 = blockIdx.x * 64;
    const int tid  = threadIdx.x;
    const int w    = tid >> 5;
    const int wr   = w & 1;        // row half (0/1)
    const int wc   = w >> 1;       // col quarter (0..3)
    const int lane = tid & 31;
    const int g    = lane >> 2;
    const int q    = lane & 3;

    float acc[2][6][4] = {};

    {
        #pragma unroll
        for (int j = 0; j < 2; j++) {
            int idx = tid + 256*j;
            int r = idx >> 3, c4 = (idx & 7) * 4;
            cp16((uint32_t)__cvta_generic_to_shared(&Xs[r*XST + c4]),
                 &x[(size_t)(row0 + r)*C_ + c4]);
        }
        #pragma unroll
        for (int j = 0; j < 3; j++) {
            int idx = tid + 256*j;
            int r = idx >> 2, c4 = (idx & 3) * 4;
            cp16((uint32_t)__cvta_generic_to_shared(&Ws[r*WST + c4]),
                 &g_wh[((size_t)r << 9) + c4]);
        }
        asm volatile("cp.async.commit_group;");
    }

    for (int ch = 0; ch < 32; ch++) {
        const int p = ch & 1;
        if (ch + 1 < 32) {
            const int k0f = (ch + 1) * 32;
            const int k0w = (ch + 1) * 16;
            const int pn = p ^ 1;
            #pragma unroll
            for (int j = 0; j < 2; j++) {
                int idx = tid + 256*j;
                int r = idx >> 3, c4 = (idx & 7) * 4;
                cp16((uint32_t)__cvta_generic_to_shared(&Xs[pn*XBUF + r*XST + c4]),
                     &x[(size_t)(row0 + r)*C_ + k0f + c4]);
            }
            #pragma unroll
            for (int j = 0; j < 3; j++) {
                int idx = tid + 256*j;
                int r = idx >> 2, c4 = (idx & 3) * 4;
                cp16((uint32_t)__cvta_generic_to_shared(&Ws[pn*WBUF + r*WST + c4]),
                     &g_wh[((size_t)r << 9) + k0w + c4]);
            }
            asm volatile("cp.async.commit_group;");
            asm volatile("cp.async.wait_group 1;");
        } else {
            asm volatile("cp.async.wait_group 0;");
        }
        __syncthreads();

        const float*    Xc = Xs + p*XBUF;
        const uint32_t* Wc = Ws + p*WBUF;

        #pragma unroll
        for (int ks = 0; ks < 2; ks++) {
            uint32_t a[2][4];
            #pragma unroll
            for (int m = 0; m < 2; m++) {
                int row = wr*32 + m*16 + g;
                float2 f0 = *reinterpret_cast<const float2*>(&Xc[row*XST + ks*16 + 2*q]);
                float2 f1 = *reinterpret_cast<const float2*>(&Xc[(row+8)*XST + ks*16 + 2*q]);
                float2 f2 = *reinterpret_cast<const float2*>(&Xc[row*XST + ks*16 + 8 + 2*q]);
                float2 f3 = *reinterpret_cast<const float2*>(&Xc[(row+8)*XST + ks*16 + 8 + 2*q]);
                a[m][0] = h2(f0.x, f0.y);
                a[m][1] = h2(f1.x, f1.y);
                a[m][2] = h2(f2.x, f2.y);
                a[m][3] = h2(f3.x, f3.y);
            }
            #pragma unroll
            for (int j = 0; j < 6; j++) {
                int rn = wc*48 + j*8 + g;
                uint32_t b0 = Wc[rn*WST + ks*8 + q];
                uint32_t b1 = Wc[rn*WST + ks*8 + 4 + q];
                #pragma unroll
                for (int m = 0; m < 2; m++)
                    mma_fp16(acc[m][j], a[m], b0, b1);
            }
        }
        __syncthreads();
    }

    // epilogue: sel 0 -> K, 1 -> Q (scaled), 2 -> V
    const float scale = 0.03125f;
    #pragma unroll
    for (int m = 0; m < 2; m++) {
        #pragma unroll
        for (int j = 0; j < 6; j++) {
            int gcol = wc*48 + j*8 + q*2;
            int sel  = gcol >> 6;
            int col  = gcol & 63;
            int row  = row0 + wr*32 + m*16 + g;
            int bb = row >> 12, t = row & 4095;
            int kt = t >> 6, jj = t & 63;
            float a0 = acc[m][j][0], a1 = acc[m][j][1];
            float a2 = acc[m][j][2], a3 = acc[m][j][3];
            if (sel == 0) {
                uint32_t* base = g_kh + (((size_t)bb*64 + kt) << 11);
                int kk = col >> 4, r = col & 15, hi = r >> 3, qq = (r & 7) >> 1;
                base[qq*8 + (jj&7)     + 32*hi + 64*(jj>>3)     + 512*kk] = h2(a0, a1);
                base[qq*8 + ((jj+8)&7) + 32*hi + 64*((jj+8)>>3) + 512*kk] = h2(a2, a3);
            } else if (sel == 1) {
                g_qh[(size_t)row*32     + (col>>1)] = h2(a0*scale, a1*scale);
                g_qh[(size_t)(row+8)*32 + (col>>1)] = h2(a2*scale, a3*scale);
            } else {
                float p0 = __shfl_xor_sync(0xffffffff, a0, 4);
                float p1 = __shfl_xor_sync(0xffffffff, a1, 4);
                float p2 = __shfl_xor_sync(0xffffffff, a2, 4);
                float p3 = __shfl_xor_sync(0xffffffff, a3, 4);
                if ((g & 1) == 0) {
                    uint32_t* base = g_vh + (((size_t)bb*64 + kt) << 11);
                    {
                        int kk = jj >> 4, r = jj & 15, hi = r >> 3, qq = (r & 7) >> 1;
                        int w0 = qq*8 + 32*hi + 512*kk;
                        base[w0 + (col&7)     + 64*(col>>3)]     = h2(a0, p0);
                        base[w0 + ((col+1)&7) + 64*((col+1)>>3)] = h2(a1, p1);
                    }
                    {
                        int j8 = jj + 8;
                        int kk = j8 >> 4, r = j8 & 15, hi = r >> 3, qq = (r & 7) >> 1;
                        int w0 = qq*8 + 32*hi + 512*kk;
                        base[w0 + (col&7)     + 64*(col>>3)]     = h2(a2, p2);
                        base[w0 + ((col+1)&7) + 64*((col+1)>>3)] = h2(a3, p3);
                    }
                }
            }
        }
    }
}

// ---------------------------------------------------------------------------
// Kernel 2: flash attention partial pass (R9 structure + diagonal block-skip).
// ---------------------------------------------------------------------------
#define PST 36
#define TILE_W 2048

__global__ __launch_bounds__(256, 2) void attn_part_kernel()
{
    extern __shared__ uint32_t sm[];
    uint32_t* Kf = sm;                       // [2][2048]
    uint32_t* Vf = sm + 2*TILE_W;            // [2][2048]
    uint32_t* Ps = sm + 4*TILE_W;            // [128][PST] (Q staging)

    const int id = blockIdx.x;
    const int b  = blockIdx.y;

    int qt = 0, chunk = id;
    while (chunk >= ((2*qt + 9) >> 3)) { chunk -= (2*qt + 9) >> 3; qt++; }

    const int kb_last = 2*qt + 1;
    const int kb_lo = chunk * GTILES;
    const int kb_hi = min(kb_last, kb_lo + GTILES - 1);

    const int tid = threadIdx.x;
    const int w   = tid >> 5;
    const int lane = tid & 31;
    const int g   = lane >> 2;
    const int q   = lane & 3;
    const int bgq = q*8 + g;

    // stage Q (pre-scaled fp16 words)
    const uint32_t* qg = g_qh + ((size_t)b * T_ + (size_t)qt * 128) * 32;
    for (int i = tid * 4; i < 128 * 32; i += 1024) {
        int r = i >> 5, cc = i & 31;
        *reinterpret_cast<uint4*>(&Ps[r * PST + cc]) =
            *reinterpret_cast<const uint4*>(&qg[r * 32 + cc]);
    }

    const uint32_t* ktile = g_kh + (((size_t)b*64 + kb_lo) << 11);
    const uint32_t* vtile = g_vh + (((size_t)b*64 + kb_lo) << 11);

    #pragma unroll
    for (int j = 0; j < 2; j++) {
        int off = (tid + 256*j) * 4;
        cp16((uint32_t)__cvta_generic_to_shared(&Kf[off]), ktile + off);
        cp16((uint32_t)__cvta_generic_to_shared(&Vf[off]), vtile + off);
    }
    asm volatile("cp.async.commit_group;");

    __syncthreads();

    uint32_t qa[4][4];
    #pragma unroll
    for (int kk = 0; kk < 4; kk++) {
        int row = w * 16 + g;
        qa[kk][0] = Ps[row * PST + kk * 8 + q];
        qa[kk][1] = Ps[(row + 8) * PST + kk * 8 + q];
        qa[kk][2] = Ps[row * PST + kk * 8 + 4 + q];
        qa[kk][3] = Ps[(row + 8) * PST + kk * 8 + 4 + q];
    }

    float o[8][4] = {};
    float l0 = 0.0f, l1 = 0.0f;

    for (int kb = kb_lo; kb <= kb_hi; kb++) {
        const int p = (kb - kb_lo) & 1;
        if (kb < kb_hi) {
            const int pn = p ^ 1;
            const uint32_t* kt2 = g_kh + (((size_t)b*64 + kb + 1) << 11);
            const uint32_t* vt2 = g_vh + (((size_t)b*64 + kb + 1) << 11);
            #pragma unroll
            for (int j = 0; j < 2; j++) {
                int off = (tid + 256*j) * 4;
                cp16((uint32_t)__cvta_generic_to_shared(&Kf[pn*TILE_W + off]), kt2 + off);
                cp16((uint32_t)__cvta_generic_to_shared(&Vf[pn*TILE_W + off]), vt2 + off);
            }
            asm volatile("cp.async.commit_group;");
            asm volatile("cp.async.wait_group 1;");
        } else {
            asm volatile("cp.async.wait_group 0;");
        }
        __syncthreads();

        // fully masked warps on the last diagonal tile: skip compute
        if (kb == kb_last && w < 4) { __syncthreads(); continue; }

        // warp-level unmasked local-column bound for diagonal tiles
        int kmax = 9999;
        if (kb >= 2*qt)
            kmax = (qt*128 + w*16 + 15) - kb*64;

        const uint32_t* Kc = Kf + p*TILE_W + bgq;
        const uint32_t* Vc = Vf + p*TILE_W + bgq;

        // S = Q @ K^T (skip fully-masked 8-col blocks)
        float s[8][4] = {};
        #pragma unroll
        for (int kk = 0; kk < 4; kk++) {
            #pragma unroll
            for (int n = 0; n < 8; n++) {
                if (n*8 <= kmax) {
                    uint32_t b0 = Kc[512*kk + 64*n];
                    uint32_t b1 = Kc[512*kk + 64*n + 32];
                    mma_fp16(s[n], qa[kk], b0, b1);
                }
            }
        }

        // causal mask on diagonal-crossing k-tiles
        if (kb >= 2*qt) {
            int grow = qt*128 + w*16 + g;
            #pragma unroll
            for (int n = 0; n < 8; n++) {
                int gc = kb*64 + n*8 + q*2;
                if (gc     > grow)     s[n][0] = -1e30f;
                if (gc + 1 > grow)     s[n][1] = -1e30f;
                if (gc     > grow + 8) s[n][2] = -1e30f;
                if (gc + 1 > grow + 8) s[n][3] = -1e30f;
            }
        }

        // fixed-max softmax
        float sum0 = 0.0f, sum1 = 0.0f;
        #pragma unroll
        for (int n = 0; n < 8; n++) {
            s[n][0] = __expf(s[n][0]);
            s[n][1] = __expf(s[n][1]);
            s[n][2] = __expf(s[n][2]);
            s[n][3] = __expf(s[n][3]);
            sum0 += s[n][0] + s[n][1];
            sum1 += s[n][2] + s[n][3];
        }
        sum0 += __shfl_xor_sync(0xffffffff, sum0, 1);
        sum0 += __shfl_xor_sync(0xffffffff, sum0, 2);
        sum1 += __shfl_xor_sync(0xffffffff, sum1, 1);
        sum1 += __shfl_xor_sync(0xffffffff, sum1, 2);
        l0 += sum0;
        l1 += sum1;

        // P in registers -> O += P @ V (skip all-zero 16-key blocks)
        #pragma unroll
        for (int kk = 0; kk < 4; kk++) {
            if (kk*16 <= kmax) {
                uint32_t pa[4];
                pa[0] = h2(s[2*kk][0],   s[2*kk][1]);
                pa[1] = h2(s[2*kk][2],   s[2*kk][3]);
                pa[2] = h2(s[2*kk+1][0], s[2*kk+1][1]);
                pa[3] = h2(s[2*kk+1][2], s[2*kk+1][3]);
                #pragma unroll
                for (int n = 0; n < 8; n++) {
                    uint32_t b0 = Vc[512*kk + 64*n];
                    uint32_t b1 = Vc[512*kk + 64*n + 32];
                    mma_fp16(o[n], pa, b0, b1);
                }
            }
        }
        __syncthreads();
    }

    // accumulate partials atomically
    const int r0 = qt*128 + w*16 + g;
    float* ao0 = g_acc + ((size_t)(b*T_ + r0)) * H_;
    float* ao1 = g_acc + ((size_t)(b*T_ + r0 + 8)) * H_;
    #pragma unroll
    for (int n = 0; n < 8; n++) {
        int col = n * 8 + q * 2;
        atomicAdd(&ao0[col],     o[n][0]);
        atomicAdd(&ao0[col + 1], o[n][1]);
        atomicAdd(&ao1[col],     o[n][2]);
        atomicAdd(&ao1[col + 1], o[n][3]);
    }
    if (q == 0) {
        atomicAdd(&g_lacc[b*T_ + r0],     l0);
        atomicAdd(&g_lacc[b*T_ + r0 + 8], l1);
    }
}

// ---------------------------------------------------------------------------
// Kernel 3: normalize. out[row][h] = g_acc[row][h] / g_lacc[row].
// ---------------------------------------------------------------------------
__global__ __launch_bounds__(256) void attn_norm_kernel(float* __restrict__ out)
{
    int idx = blockIdx.x * 256 + threadIdx.x;
    int row = idx >> 4;
    int c4  = (idx & 15) * 4;
    float invL = 1.0f / g_lacc[row];
    float4 v = *reinterpret_cast<const float4*>(&g_acc[(size_t)row * H_ + c4]);
    v.x *= invL; v.y *= invL; v.z *= invL; v.w *= invL;
    *reinterpret_cast<float4*>(&out[(size_t)row * H_ + c4]) = v;
}

// ---------------------------------------------------------------------------
extern "C" void kernel_launch(void* const* d_in, const int* in_sizes, int n_in,
                              void* d_out, int out_size)
{
    const float* x  = (const float*)d_in[0];
    const float* Wk = (const float*)d_in[1];
    const float* Wq = (const float*)d_in[2];
    const float* Wv = (const float*)d_in[3];
    float* out = (float*)d_out;

    void* acc_ptr = nullptr;
    void* lacc_ptr = nullptr;
    cudaGetSymbolAddress(&acc_ptr, g_acc);
    cudaGetSymbolAddress(&lacc_ptr, g_lacc);
    cudaMemsetAsync(acc_ptr, 0, sizeof(float)*B_*T_*H_);
    cudaMemsetAsync(lacc_ptr, 0, sizeof(float)*B_*T_);

    wconv_kernel<<<384, 256>>>(Wk, Wq, Wv);

    const int qkv_smem = (2*XBUF) * (int)sizeof(float) + (2*WBUF) * (int)sizeof(uint32_t);
    cudaFuncSetAttribute(qkv_kernel,
                         cudaFuncAttributeMaxDynamicSharedMemorySize, qkv_smem);
    qkv_kernel<<<(B_*T_)/64, 256, qkv_smem>>>(x);

    const int attn_smem = (4*TILE_W + 128*PST) * (int)sizeof(uint32_t);
    cudaFuncSetAttribute(attn_part_kernel,
                         cudaFuncAttributeMaxDynamicSharedMemorySize, attn_smem);
    attn_part_kernel<<<dim3(NPART, B_), 256, attn_smem>>>();

    attn_norm_kernel<<<(B_*T_*16)/256, 256>>>(out);
}

// round 14
// speedup vs baseline: 1.0567x; 1.0563x over previous
#include <cuda_runtime.h>
#include <cuda_fp16.h>
#include <cstdint>

#define B_ 4
#define T_ 4096
#define C_ 1024
#define H_ 64

#define NQT 32          // 128-query tiles
#define GTILES 8        // k-tiles per attention CTA
#define NPART 144       // sum over qt of ceil((2*qt+2)/8)

// Q: fp16 pairs (half2 words along d), pre-scaled: [b*t][32 words]
__device__ uint32_t g_qh[B_*T_*32];
// K: per 64-key tile, half2-packed B-frag swizzle (pairs along d)
__device__ uint32_t g_kh[B_*64*2048];
// V: pairs along key j
__device__ uint32_t g_vh[B_*64*2048];
// W fp16: [sel][n][k/2] half2 along k
__device__ uint32_t g_wh[3*64*512];

__device__ float g_acc[B_*T_*H_];   // 4 MB unnormalized O accumulator
__device__ float g_lacc[B_*T_];     // 64 KB l accumulator

__device__ __forceinline__ uint32_t h2(float x, float y) {
    __half2 h = __floats2half2_rn(x, y);
    return *reinterpret_cast<uint32_t*>(&h);
}

__device__ __forceinline__ void mma_fp16(float c[4], const uint32_t a[4],
                                         uint32_t b0, uint32_t b1) {
    asm volatile(
        "mma.sync.aligned.m16n8k16.row.col.f32.f16.f16.f32 "
        "{%0,%1,%2,%3}, {%4,%5,%6,%7}, {%8,%9}, {%0,%1,%2,%3};"
        : "+f"(c[0]), "+f"(c[1]), "+f"(c[2]), "+f"(c[3])
        : "r"(a[0]), "r"(a[1]), "r"(a[2]), "r"(a[3]), "r"(b0), "r"(b1));
}

__device__ __forceinline__ void cp16(uint32_t dst, const void* src) {
    asm volatile("cp.async.cg.shared.global [%0], [%1], 16;" :: "r"(dst), "l"(src));
}

// ---------------------------------------------------------------------------
// Kernel 0: W -> fp16 half2 words, [sel][n][k/2]
// ---------------------------------------------------------------------------
__global__ __launch_bounds__(256) void wconv_kernel(
    const float* __restrict__ Wk, const float* __restrict__ Wq,
    const float* __restrict__ Wv)
{
    int idx = blockIdx.x * 256 + threadIdx.x;
    int wi = idx >> 15;
    int r  = idx & 32767;
    int n  = r >> 9;
    int k2 = r & 511;
    const float* W = (wi == 0) ? Wk : ((wi == 1) ? Wq : Wv);
    g_wh[((size_t)(wi*64 + n) << 9) + k2] =
        h2(W[(2*k2)*64 + n], W[(2*k2 + 1)*64 + n]);
}

// ---------------------------------------------------------------------------
// Kernel 1: fused QKV, fp16 mma m16n8k16. 128 threads / 4 warps (R9 shape).
// X fp32 in smem (cvt at frag build), W fp16. cp.async double-buffered.
// ---------------------------------------------------------------------------
#define XST 36
#define WST 20
#define XBUF (64*XST)
#define WBUF (192*WST)

__global__ __launch_bounds__(128) void qkv_kernel(const float* __restrict__ x)
{
    extern __shared__ float smf[];
    float*    Xs = smf;
    uint32_t* Ws = (uint32_t*)(smf + 2*XBUF);

    const int row0 = blockIdx.x * 64;
    const int tid  = threadIdx.x;
    const int w    = tid >> 5;
    const int lane = tid & 31;
    const int g    = lane >> 2;
    const int q    = lane & 3;

    float acc[4][6][4] = {};

    {
        #pragma unroll
        for (int j = 0; j < 4; j++) {
            int idx = tid + 128*j;
            int r = idx >> 3, c4 = (idx & 7) * 4;
            cp16((uint32_t)__cvta_generic_to_shared(&Xs[r*XST + c4]),
                 &x[(size_t)(row0 + r)*C_ + c4]);
        }
        #pragma unroll
        for (int j = 0; j < 6; j++) {
            int idx = tid + 128*j;
            int r = idx >> 2, c4 = (idx & 3) * 4;
            cp16((uint32_t)__cvta_generic_to_shared(&Ws[r*WST + c4]),
                 &g_wh[((size_t)r << 9) + c4]);
        }
        asm volatile("cp.async.commit_group;");
    }

    for (int ch = 0; ch < 32; ch++) {
        const int p = ch & 1;
        if (ch + 1 < 32) {
            const int k0f = (ch + 1) * 32;
            const int k0w = (ch + 1) * 16;
            const int pn = p ^ 1;
            #pragma unroll
            for (int j = 0; j < 4; j++) {
                int idx = tid + 128*j;
                int r = idx >> 3, c4 = (idx & 7) * 4;
                cp16((uint32_t)__cvta_generic_to_shared(&Xs[pn*XBUF + r*XST + c4]),
                     &x[(size_t)(row0 + r)*C_ + k0f + c4]);
            }
            #pragma unroll
            for (int j = 0; j < 6; j++) {
                int idx = tid + 128*j;
                int r = idx >> 2, c4 = (idx & 3) * 4;
                cp16((uint32_t)__cvta_generic_to_shared(&Ws[pn*WBUF + r*WST + c4]),
                     &g_wh[((size_t)r << 9) + k0w + c4]);
            }
            asm volatile("cp.async.commit_group;");
            asm volatile("cp.async.wait_group 1;");
        } else {
            asm volatile("cp.async.wait_group 0;");
        }
        __syncthreads();

        const float*    Xc = Xs + p*XBUF;
        const uint32_t* Wc = Ws + p*WBUF;

        #pragma unroll
        for (int ks = 0; ks < 2; ks++) {
            uint32_t a[4][4];
            #pragma unroll
            for (int m = 0; m < 4; m++) {
                int row = m*16 + g;
                float2 f0 = *reinterpret_cast<const float2*>(&Xc[row*XST + ks*16 + 2*q]);
                float2 f1 = *reinterpret_cast<const float2*>(&Xc[(row+8)*XST + ks*16 + 2*q]);
                float2 f2 = *reinterpret_cast<const float2*>(&Xc[row*XST + ks*16 + 8 + 2*q]);
                float2 f3 = *reinterpret_cast<const float2*>(&Xc[(row+8)*XST + ks*16 + 8 + 2*q]);
                a[m][0] = h2(f0.x, f0.y);
                a[m][1] = h2(f1.x, f1.y);
                a[m][2] = h2(f2.x, f2.y);
                a[m][3] = h2(f3.x, f3.y);
            }
            #pragma unroll
            for (int j = 0; j < 6; j++) {
                int rn = w*48 + j*8 + g;
                uint32_t b0 = Wc[rn*WST + ks*8 + q];
                uint32_t b1 = Wc[rn*WST + ks*8 + 4 + q];
                #pragma unroll
                for (int m = 0; m < 4; m++)
                    mma_fp16(acc[m][j], a[m], b0, b1);
            }
        }
        __syncthreads();
    }

    // epilogue: sel 0 -> K, 1 -> Q (scaled), 2 -> V
    const float scale = 0.03125f;
    #pragma unroll
    for (int m = 0; m < 4; m++) {
        #pragma unroll
        for (int j = 0; j < 6; j++) {
            int gcol = w*48 + j*8 + q*2;
            int sel  = gcol >> 6;
            int col  = gcol & 63;
            int row  = row0 + m*16 + g;
            int bb = row >> 12, t = row & 4095;
            int kt = t >> 6, jj = t & 63;
            float a0 = acc[m][j][0], a1 = acc[m][j][1];
            float a2 = acc[m][j][2], a3 = acc[m][j][3];
            if (sel == 0) {
                uint32_t* base = g_kh + (((size_t)bb*64 + kt) << 11);
                int kk = col >> 4, r = col & 15, hi = r >> 3, qq = (r & 7) >> 1;
                base[qq*8 + (jj&7)     + 32*hi + 64*(jj>>3)     + 512*kk] = h2(a0, a1);
                base[qq*8 + ((jj+8)&7) + 32*hi + 64*((jj+8)>>3) + 512*kk] = h2(a2, a3);
            } else if (sel == 1) {
                g_qh[(size_t)row*32     + (col>>1)] = h2(a0*scale, a1*scale);
                g_qh[(size_t)(row+8)*32 + (col>>1)] = h2(a2*scale, a3*scale);
            } else {
                float p0 = __shfl_xor_sync(0xffffffff, a0, 4);
                float p1 = __shfl_xor_sync(0xffffffff, a1, 4);
                float p2 = __shfl_xor_sync(0xffffffff, a2, 4);
                float p3 = __shfl_xor_sync(0xffffffff, a3, 4);
                if ((g & 1) == 0) {
                    uint32_t* base = g_vh + (((size_t)bb*64 + kt) << 11);
                    {
                        int kk = jj >> 4, r = jj & 15, hi = r >> 3, qq = (r & 7) >> 1;
                        int w0 = qq*8 + 32*hi + 512*kk;
                        base[w0 + (col&7)     + 64*(col>>3)]     = h2(a0, p0);
                        base[w0 + ((col+1)&7) + 64*((col+1)>>3)] = h2(a1, p1);
                    }
                    {
                        int j8 = jj + 8;
                        int kk = j8 >> 4, r = j8 & 15, hi = r >> 3, qq = (r & 7) >> 1;
                        int w0 = qq*8 + 32*hi + 512*kk;
                        base[w0 + (col&7)     + 64*(col>>3)]     = h2(a2, p2);
                        base[w0 + ((col+1)&7) + 64*((col+1)>>3)] = h2(a3, p3);
                    }
                }
            }
        }
    }
}

// ---------------------------------------------------------------------------
// Kernel 2: flash attention partial pass (R9 structure + diagonal block-skip)
// ---------------------------------------------------------------------------
#define PST 36
#define TILE_W 2048

__global__ __launch_bounds__(256, 2) void attn_part_kernel()
{
    extern __shared__ uint32_t sm[];
    uint32_t* Kf = sm;                       // [2][2048]
    uint32_t* Vf = sm + 2*TILE_W;            // [2][2048]
    uint32_t* Ps = sm + 4*TILE_W;            // [128][PST] (Q staging)

    const int id = blockIdx.x;
    const int b  = blockIdx.y;

    int qt = 0, chunk = id;
    while (chunk >= ((2*qt + 9) >> 3)) { chunk -= (2*qt + 9) >> 3; qt++; }

    const int kb_last = 2*qt + 1;
    const int kb_lo = chunk * GTILES;
    const int kb_hi = min(kb_last, kb_lo + GTILES - 1);

    const int tid = threadIdx.x;
    const int w   = tid >> 5;
    const int lane = tid & 31;
    const int g   = lane >> 2;
    const int q   = lane & 3;
    const int bgq = q*8 + g;

    // stage Q (pre-scaled fp16 words)
    const uint32_t* qg = g_qh + ((size_t)b * T_ + (size_t)qt * 128) * 32;
    for (int i = tid * 4; i < 128 * 32; i += 1024) {
        int r = i >> 5, cc = i & 31;
        *reinterpret_cast<uint4*>(&Ps[r * PST + cc]) =
            *reinterpret_cast<const uint4*>(&qg[r * 32 + cc]);
    }

    const uint32_t* ktile = g_kh + (((size_t)b*64 + kb_lo) << 11);
    const uint32_t* vtile = g_vh + (((size_t)b*64 + kb_lo) << 11);

    #pragma unroll
    for (int j = 0; j < 2; j++) {
        int off = (tid + 256*j) * 4;
        cp16((uint32_t)__cvta_generic_to_shared(&Kf[off]), ktile + off);
        cp16((uint32_t)__cvta_generic_to_shared(&Vf[off]), vtile + off);
    }
    asm volatile("cp.async.commit_group;");

    __syncthreads();

    uint32_t qa[4][4];
    #pragma unroll
    for (int kk = 0; kk < 4; kk++) {
        int row = w * 16 + g;
        qa[kk][0] = Ps[row * PST + kk * 8 + q];
        qa[kk][1] = Ps[(row + 8) * PST + kk * 8 + q];
        qa[kk][2] = Ps[row * PST + kk * 8 + 4 + q];
        qa[kk][3] = Ps[(row + 8) * PST + kk * 8 + 4 + q];
    }

    float o[8][4] = {};
    float l0 = 0.0f, l1 = 0.0f;

    for (int kb = kb_lo; kb <= kb_hi; kb++) {
        const int p = (kb - kb_lo) & 1;
        if (kb < kb_hi) {
            const int pn = p ^ 1;
            const uint32_t* kt2 = g_kh + (((size_t)b*64 + kb + 1) << 11);
            const uint32_t* vt2 = g_vh + (((size_t)b*64 + kb + 1) << 11);
            #pragma unroll
            for (int j = 0; j < 2; j++) {
                int off = (tid + 256*j) * 4;
                cp16((uint32_t)__cvta_generic_to_shared(&Kf[pn*TILE_W + off]), kt2 + off);
                cp16((uint32_t)__cvta_generic_to_shared(&Vf[pn*TILE_W + off]), vt2 + off);
            }
            asm volatile("cp.async.commit_group;");
            asm volatile("cp.async.wait_group 1;");
        } else {
            asm volatile("cp.async.wait_group 0;");
        }
        __syncthreads();

        // fully masked warps on the last diagonal tile: skip compute
        if (kb == kb_last && w < 4) { __syncthreads(); continue; }

        // warp-level unmasked local-column bound for diagonal tiles
        int kmax = 9999;
        if (kb >= 2*qt)
            kmax = (qt*128 + w*16 + 15) - kb*64;   // >= 15 for surviving warps

        const uint32_t* Kc = Kf + p*TILE_W + bgq;
        const uint32_t* Vc = Vf + p*TILE_W + bgq;

        // S = Q @ K^T (skip fully-masked 8-col blocks)
        float s[8][4] = {};
        #pragma unroll
        for (int kk = 0; kk < 4; kk++) {
            #pragma unroll
            for (int n = 0; n < 8; n++) {
                if (n*8 <= kmax) {
                    uint32_t b0 = Kc[512*kk + 64*n];
                    uint32_t b1 = Kc[512*kk + 64*n + 32];
                    mma_fp16(s[n], qa[kk], b0, b1);
                }
            }
        }

        // causal mask on diagonal-crossing k-tiles
        if (kb >= 2*qt) {
            int grow = qt*128 + w*16 + g;
            #pragma unroll
            for (int n = 0; n < 8; n++) {
                int gc = kb*64 + n*8 + q*2;
                if (gc     > grow)     s[n][0] = -1e30f;
                if (gc + 1 > grow)     s[n][1] = -1e30f;
                if (gc     > grow + 8) s[n][2] = -1e30f;
                if (gc + 1 > grow + 8) s[n][3] = -1e30f;
            }
        }

        // fixed-max softmax
        float sum0 = 0.0f, sum1 = 0.0f;
        #pragma unroll
        for (int n = 0; n < 8; n++) {
            s[n][0] = __expf(s[n][0]);
            s[n][1] = __expf(s[n][1]);
            s[n][2] = __expf(s[n][2]);
            s[n][3] = __expf(s[n][3]);
            sum0 += s[n][0] + s[n][1];
            sum1 += s[n][2] + s[n][3];
        }
        sum0 += __shfl_xor_sync(0xffffffff, sum0, 1);
        sum0 += __shfl_xor_sync(0xffffffff, sum0, 2);
        sum1 += __shfl_xor_sync(0xffffffff, sum1, 1);
        sum1 += __shfl_xor_sync(0xffffffff, sum1, 2);
        l0 += sum0;
        l1 += sum1;

        // P in registers -> O += P @ V (skip all-zero 16-key blocks)
        #pragma unroll
        for (int kk = 0; kk < 4; kk++) {
            if (kk*16 <= kmax) {
                uint32_t pa[4];
                pa[0] = h2(s[2*kk][0],   s[2*kk][1]);
                pa[1] = h2(s[2*kk][2],   s[2*kk][3]);
                pa[2] = h2(s[2*kk+1][0], s[2*kk+1][1]);
                pa[3] = h2(s[2*kk+1][2], s[2*kk+1][3]);
                #pragma unroll
                for (int n = 0; n < 8; n++) {
                    uint32_t b0 = Vc[512*kk + 64*n];
                    uint32_t b1 = Vc[512*kk + 64*n + 32];
                    mma_fp16(o[n], pa, b0, b1);
                }
            }
        }
        __syncthreads();
    }

    // accumulate partials atomically
    const int r0 = qt*128 + w*16 + g;
    float* ao0 = g_acc + ((size_t)(b*T_ + r0)) * H_;
    float* ao1 = g_acc + ((size_t)(b*T_ + r0 + 8)) * H_;
    #pragma unroll
    for (int n = 0; n < 8; n++) {
        int col = n * 8 + q * 2;
        atomicAdd(&ao0[col],     o[n][0]);
        atomicAdd(&ao0[col + 1], o[n][1]);
        atomicAdd(&ao1[col],     o[n][2]);
        atomicAdd(&ao1[col + 1], o[n][3]);
    }
    if (q == 0) {
        atomicAdd(&g_lacc[b*T_ + r0],     l0);
        atomicAdd(&g_lacc[b*T_ + r0 + 8], l1);
    }
}

// ---------------------------------------------------------------------------
// Kernel 3: normalize. out[row][h] = g_acc[row][h] / g_lacc[row].
// ---------------------------------------------------------------------------
__global__ __launch_bounds__(256) void attn_norm_kernel(float* __restrict__ out)
{
    int idx = blockIdx.x * 256 + threadIdx.x;
    int row = idx >> 4;
    int c4  = (idx & 15) * 4;
    float invL = 1.0f / g_lacc[row];
    float4 v = *reinterpret_cast<const float4*>(&g_acc[(size_t)row * H_ + c4]);
    v.x *= invL; v.y *= invL; v.z *= invL; v.w *= invL;
    *reinterpret_cast<float4*>(&out[(size_t)row * H_ + c4]) = v;
}

// ---------------------------------------------------------------------------
extern "C" void kernel_launch(void* const* d_in, const int* in_sizes, int n_in,
                              void* d_out, int out_size)
{
    const float* x  = (const float*)d_in[0];
    const float* Wk = (const float*)d_in[1];
    const float* Wq = (const float*)d_in[2];
    const float* Wv = (const float*)d_in[3];
    float* out = (float*)d_out;

    void* acc_ptr = nullptr;
    void* lacc_ptr = nullptr;
    cudaGetSymbolAddress(&acc_ptr, g_acc);
    cudaGetSymbolAddress(&lacc_ptr, g_lacc);
    cudaMemsetAsync(acc_ptr, 0, sizeof(float)*B_*T_*H_);
    cudaMemsetAsync(lacc_ptr, 0, sizeof(float)*B_*T_);

    wconv_kernel<<<384, 256>>>(Wk, Wq, Wv);

    const int qkv_smem = (2*XBUF) * (int)sizeof(float) + (2*WBUF) * (int)sizeof(uint32_t);
    cudaFuncSetAttribute(qkv_kernel,
                         cudaFuncAttributeMaxDynamicSharedMemorySize, qkv_smem);
    qkv_kernel<<<(B_*T_)/64, 128, qkv_smem>>>(x);

    const int attn_smem = (4*TILE_W + 128*PST) * (int)sizeof(uint32_t);
    cudaFuncSetAttribute(attn_part_kernel,
                         cudaFuncAttributeMaxDynamicSharedMemorySize, attn_smem);
    attn_part_kernel<<<dim3(NPART, B_), 256, attn_smem>>>();

    attn_norm_kernel<<<(B_*T_*16)/256, 256>>>(out);
}